// round 12
// baseline (speedup 1.0000x reference)
#include <cuda_runtime.h>
#include <cuda_bf16.h>

// Problem constants (match reference_code)
#define N_NODES 100000
#define N_EDGES 3200000
#define D_FEAT  16
#define N_LAYERS 12

#define SCAN_B 1024
#define NB ((N_NODES + SCAN_B - 1) / SCAN_B)

// ---- scratch (device globals; no allocation allowed) ----
__device__ float  g_h[2][N_NODES * D_FEAT];     // ping-pong scaled-feature buffers (hhat = inv_sqrt * h)
__device__ float  g_inv_sqrt[N_NODES];
__device__ float  g_self[N_NODES];              // inv_sqrt^2 = 1/deg
__device__ int    g_cnt[N_NODES];               // dst-degree counts
__device__ int    g_nonisol[N_NODES];           // set only from src side; dst side implied by cnt>0
__device__ int    g_row[N_NODES + 1];           // CSR row offsets (by dst)
__device__ int    g_cursor[N_NODES];
__device__ int    g_src[N_EDGES];               // src index per CSR slot (weight eliminated)
__device__ int    g_blocksums[NB];

// ---- 1. init counters ----
__global__ void k_init() {
    int i = blockIdx.x * blockDim.x + threadIdx.x;
    if (i < N_NODES) { g_cnt[i] = 0; g_nonisol[i] = 0; }
}

// ---- 2. count dst occurrences + mark src non-isolation (2 edges/thread) ----
__global__ void k_count(const int* __restrict__ src, const int* __restrict__ dst) {
    int t = blockIdx.x * blockDim.x + threadIdx.x;
    if (t < N_EDGES / 2) {
        int2 s2 = ((const int2*)src)[t];
        int2 d2 = ((const int2*)dst)[t];
        atomicAdd(&g_cnt[d2.x], 1);
        atomicAdd(&g_cnt[d2.y], 1);
        g_nonisol[s2.x] = 1;
        g_nonisol[s2.y] = 1;
    }
}

// ---- 3a. per-block exclusive scan of g_cnt -> g_row (+ fused norm coefficients) ----
__global__ void k_scan_local() {
    __shared__ int s[SCAN_B];
    int tid = threadIdx.x;
    int i = blockIdx.x * SCAN_B + tid;
    int v = (i < N_NODES) ? g_cnt[i] : 0;
    if (i < N_NODES) {
        float inv = rsqrtf((float)(1 + v));
        g_inv_sqrt[i] = inv;
        g_self[i] = inv * inv;
    }
    s[tid] = v;
    __syncthreads();
    for (int off = 1; off < SCAN_B; off <<= 1) {
        int t = (tid >= off) ? s[tid - off] : 0;
        __syncthreads();
        s[tid] += t;
        __syncthreads();
    }
    if (i < N_NODES) g_row[i] = s[tid] - v;          // exclusive
    if (tid == SCAN_B - 1) g_blocksums[blockIdx.x] = s[tid];
}

// ---- 3b. scan the 98 block sums in parallel (one 128-thread block) ----
__global__ void k_scan_block() {
    __shared__ int s[128];
    int tid = threadIdx.x;
    int v = (tid < NB) ? g_blocksums[tid] : 0;
    s[tid] = v;
    __syncthreads();
    for (int off = 1; off < 128; off <<= 1) {
        int t = (tid >= off) ? s[tid - off] : 0;
        __syncthreads();
        s[tid] += t;
        __syncthreads();
    }
    if (tid < NB) g_blocksums[tid] = s[tid] - v;     // exclusive
}

// ---- 3c. add block offsets, init cursors, cap row array ----
__global__ void k_scan_add() {
    int i = blockIdx.x * blockDim.x + threadIdx.x;
    if (i < N_NODES) {
        int r = g_row[i] + g_blocksums[i / SCAN_B];
        g_row[i] = r;
        g_cursor[i] = r;
    }
    if (i == 0) g_row[N_NODES] = N_EDGES;
}

// ---- 4. masked + pre-scaled copy: hhat0 = inv_sqrt * (masked x) ----
// non-isolated  <=>  appeared as src (g_nonisol) OR as dst (g_cnt > 0)
__global__ void k_mask(const float* __restrict__ x) {
    int j = blockIdx.x * blockDim.x + threadIdx.x;   // float4 index
    if (j < N_NODES * (D_FEAT / 4)) {
        int n = j / (D_FEAT / 4);
        float4 v = ((const float4*)x)[j];
        float sc = (g_nonisol[n] || g_cnt[n]) ? g_inv_sqrt[n] : 0.f;
        v.x *= sc; v.y *= sc; v.z *= sc; v.w *= sc;
        ((float4*)g_h[0])[j] = v;
    }
}

// ---- 5. place edges into CSR slots (src only; 2 edges/thread) ----
__global__ void k_place(const int* __restrict__ src, const int* __restrict__ dst) {
    int t = blockIdx.x * blockDim.x + threadIdx.x;
    if (t < N_EDGES / 2) {
        int2 s2 = ((const int2*)src)[t];
        int2 d2 = ((const int2*)dst)[t];
        int p0 = atomicAdd(&g_cursor[d2.x], 1);
        g_src[p0] = s2.x;
        int p1 = atomicAdd(&g_cursor[d2.y], 1);
        g_src[p1] = s2.y;
    }
}

// ---- 6. one scaled-GCN layer: warp per node, 4 lanes per edge ----
// Indices for the first 64 edges are prefetched into 2 regs/lane and
// distributed via shfl, making the 8 unrolled gather batches independent
// (no per-iteration dependent index load). deg>64 handled by tail loop.
__global__ __launch_bounds__(256) void k_prop(int sel_in, float* __restrict__ dout, int last) {
    int warp = (blockIdx.x * blockDim.x + threadIdx.x) >> 5;
    if (warp >= N_NODES) return;
    int lane = threadIdx.x & 31;
    int grp  = lane >> 2;    // 0..7: which edge in the 8-wide batch
    int f4   = lane & 3;     // 0..3: which float4 of the 16-float row

    const float* __restrict__ hin = g_h[sel_in];
    float* __restrict__ hout = dout ? dout : g_h[sel_in ^ 1];
    const float* __restrict__ fac = last ? g_inv_sqrt : g_self;

    int beg = g_row[warp];
    int deg = g_row[warp + 1] - beg;

    // prefetch up to 64 edge indices (covers essentially all nodes; Poisson(32))
    int idx0 = (lane      < deg) ? __ldg(&g_src[beg + lane])      : 0;
    int idx1 = (lane + 32 < deg) ? __ldg(&g_src[beg + lane + 32]) : 0;

    float4 acc = make_float4(0.f, 0.f, 0.f, 0.f);
    #pragma unroll
    for (int b = 0; b < 8; b++) {
        int e = b * 8 + grp;                                  // 0..63
        int s = (b < 4) ? __shfl_sync(0xffffffffu, idx0, e)
                        : __shfl_sync(0xffffffffu, idx1, e - 32);
        if (e < deg) {
            float4 v = ((const float4*)(hin + s * D_FEAT))[f4];   // independent LDG.128s
            acc.x += v.x;
            acc.y += v.y;
            acc.z += v.z;
            acc.w += v.w;
        }
    }
    // rare tail: degree > 64
    for (int e = 64 + grp; e < deg; e += 8) {
        int s = __ldg(&g_src[beg + e]);
        float4 v = ((const float4*)(hin + s * D_FEAT))[f4];
        acc.x += v.x;
        acc.y += v.y;
        acc.z += v.z;
        acc.w += v.w;
    }

    // reduce the 8 edge-groups (lane bits [4:2]) into every lane
    #pragma unroll
    for (int off = 16; off >= 4; off >>= 1) {
        acc.x += __shfl_xor_sync(0xffffffffu, acc.x, off);
        acc.y += __shfl_xor_sync(0xffffffffu, acc.y, off);
        acc.z += __shfl_xor_sync(0xffffffffu, acc.z, off);
        acc.w += __shfl_xor_sync(0xffffffffu, acc.w, off);
    }

    if (lane < 4) {
        float sc = fac[warp];
        float4 hv = ((const float4*)(hin + warp * D_FEAT))[lane];
        float4 o;
        o.x = sc * (acc.x + hv.x);
        o.y = sc * (acc.y + hv.y);
        o.z = sc * (acc.z + hv.z);
        o.w = sc * (acc.w + hv.w);
        ((float4*)(hout + warp * D_FEAT))[lane] = o;
    }
}

extern "C" void kernel_launch(void* const* d_in, const int* in_sizes, int n_in,
                              void* d_out, int out_size) {
    const float* x  = (const float*)d_in[0];
    const int*   ei = (const int*)d_in[1];
    const int* src = ei;
    const int* dst = ei + N_EDGES;
    float* out = (float*)d_out;

    const int TB = 256;
    k_init <<<(N_NODES + TB - 1) / TB, TB>>>();
    k_count<<<(N_EDGES / 2 + TB - 1) / TB, TB>>>(src, dst);
    k_scan_local<<<NB, SCAN_B>>>();
    k_scan_block<<<1, 128>>>();
    k_scan_add<<<(N_NODES + TB - 1) / TB, TB>>>();
    k_mask <<<(N_NODES * (D_FEAT / 4) + TB - 1) / TB, TB>>>(x);
    k_place<<<(N_EDGES / 2 + TB - 1) / TB, TB>>>(src, dst);

    int total_threads = N_NODES * 32;
    int blocks = (total_threads + TB - 1) / TB;
    for (int l = 0; l < N_LAYERS; l++) {
        int last = (l == N_LAYERS - 1);
        k_prop<<<blocks, TB>>>(l & 1, last ? out : nullptr, last);
    }
}